// round 4
// baseline (speedup 1.0000x reference)
#include <cuda_runtime.h>
#include <cstdint>

// NN upsample x2, NHWC fp32: (8,128,128,256) -> (8,256,256,256)
// GATHER formulation: one thread per OUTPUT float4.
// 1x LDG.128 (mostly L1/L2 hits due to 4x reuse) + 1x STG.128.
// The store stream is perfectly sequential across the grid -> ideal DRAM
// write pattern; DRAM read traffic stays at the 134 MB minimum via caches.

static constexpr int HO = 256;
static constexpr int WO = 256;
static constexpr int C4 = 256 / 4;   // 64 float4 per pixel
static constexpr long long N_OUT4 = 8LL * HO * WO * C4;  // 33,554,432

__global__ __launch_bounds__(256, 8)
void upsample2x_gather_kernel(const float4* __restrict__ in,
                              float4* __restrict__ out)
{
    long long idx = (long long)blockIdx.x * blockDim.x + threadIdx.x;

    // idx = ((b*HO + ho)*WO + wo)*C4 + c4
    int c4  = (int)(idx & (C4 - 1));     // 64
    long long t = idx >> 6;              // (b*HO + ho)*WO + wo
    int wo  = (int)(t & (WO - 1));       // 256
    long long bho = t >> 8;              // b*HO + ho
    int ho  = (int)(bho & (HO - 1));     // 256
    int b   = (int)(bho >> 8);

    // input pixel (ho/2, wo/2) in [8,128,128,C4]
    long long iidx = (((long long)(b * 128 + (ho >> 1))) * 128 + (wo >> 1)) * C4 + c4;

    out[idx] = __ldg(in + iidx);
}

extern "C" void kernel_launch(void* const* d_in, const int* in_sizes, int n_in,
                              void* d_out, int out_size)
{
    const float4* in  = (const float4*)d_in[0];
    float4*       out = (float4*)d_out;

    const int threads = 256;
    const long long blocks = N_OUT4 / threads;   // 131072
    upsample2x_gather_kernel<<<(unsigned)blocks, threads>>>(in, out);
}

// round 5
// speedup vs baseline: 1.1988x; 1.1988x over previous
#include <cuda_runtime.h>
#include <cstdint>

// NN upsample x2, NHWC fp32: (8,128,128,256) -> (8,256,256,256)
// Scatter formulation (best so far), with:
//  - 2 independent input float4 per thread (read MLP=2, 8 stores batched)
//  - streaming cache hints (__ldcs/__stcs): every byte touched exactly once
// Thread t handles input vec4 t and t + N/2 (both streams stay coalesced).

static constexpr int W   = 128;
static constexpr int C4  = 256 / 4;  // 64 float4 per pixel
static constexpr int WO  = W * 2;    // 256
static constexpr long long N_IN4 = 8LL * 128 * 128 * C4;  // 8,388,608
static constexpr long long HALF  = N_IN4 / 2;             // 4,194,304
static constexpr long long ROWS  = (long long)WO * C4;    // 16384 (output row stride)

__device__ __forceinline__ void scatter4(float4* __restrict__ out,
                                         long long idx, const float4& v)
{
    int c4 = (int)(idx & (C4 - 1));
    long long t = idx >> 6;              // (b*H + h)*W + w
    int w = (int)(t & (W - 1));
    long long bh = t >> 7;               // b*H + h

    long long o = ((2ll * bh) * WO + 2ll * w) * C4 + c4;

    __stcs(out + o,              v);     // (2h,   2w)
    __stcs(out + o + C4,         v);     // (2h,   2w+1)
    __stcs(out + o + ROWS,       v);     // (2h+1, 2w)
    __stcs(out + o + ROWS + C4,  v);     // (2h+1, 2w+1)
}

__global__ __launch_bounds__(256, 8)
void upsample2x_kernel(const float4* __restrict__ in, float4* __restrict__ out)
{
    long long i0 = (long long)blockIdx.x * blockDim.x + threadIdx.x;
    long long i1 = i0 + HALF;

    // Two independent loads in flight before any store.
    float4 v0 = __ldcs(in + i0);
    float4 v1 = __ldcs(in + i1);

    scatter4(out, i0, v0);
    scatter4(out, i1, v1);
}

extern "C" void kernel_launch(void* const* d_in, const int* in_sizes, int n_in,
                              void* d_out, int out_size)
{
    const float4* in  = (const float4*)d_in[0];
    float4*       out = (float4*)d_out;

    const int threads = 256;
    const long long blocks = HALF / threads;   // 16384
    upsample2x_kernel<<<(unsigned)blocks, threads>>>(in, out);
}

// round 10
// speedup vs baseline: 1.2093x; 1.0088x over previous
#include <cuda_runtime.h>
#include <cstdint>

// NN upsample x2, NHWC fp32: (8,128,128,256) -> (8,256,256,256)
// Scatter, one thread per input float8 (32B) — the only access width that
// accepts L2 eviction modifiers on sm_103 (.v4.b64):
//   input  (134 MB ~ L2 126 MB): ld.global.nc.L2::evict_last.v4.b64
//       -> input stays L2-resident across graph replays
//   output (537 MB streaming):   st.global.L2::evict_first.v4.b64
//       -> write stream doesn't evict the pinned input

static constexpr int W   = 128;
static constexpr int C8  = 256 / 8;  // 32 float8 per pixel
static constexpr int WO  = W * 2;    // 256
static constexpr long long N_IN8 = 8LL * 128 * 128 * C8;  // 4,194,304
static constexpr long long ROWS  = (long long)WO * C8;    // 8192

struct __align__(32) v8 { unsigned long long d0, d1, d2, d3; };

__device__ __forceinline__ v8 ldg_evict_last(const v8* p) {
    v8 v;
    asm volatile("ld.global.nc.L2::evict_last.v4.b64 {%0,%1,%2,%3}, [%4];"
                 : "=l"(v.d0), "=l"(v.d1), "=l"(v.d2), "=l"(v.d3)
                 : "l"(p));
    return v;
}

__device__ __forceinline__ void stg_evict_first(v8* p, const v8& v) {
    asm volatile("st.global.L2::evict_first.v4.b64 [%0], {%1,%2,%3,%4};"
                 :: "l"(p), "l"(v.d0), "l"(v.d1), "l"(v.d2), "l"(v.d3)
                 : "memory");
}

__global__ __launch_bounds__(256, 8)
void upsample2x_kernel(const v8* __restrict__ in, v8* __restrict__ out)
{
    long long idx = (long long)blockIdx.x * blockDim.x + threadIdx.x;

    v8 v = ldg_evict_last(in + idx);

    int c8 = (int)(idx & (C8 - 1));      // 32
    long long t = idx >> 5;              // (b*H + h)*W + w
    int w = (int)(t & (W - 1));          // 128
    long long bh = t >> 7;               // b*H + h

    long long o = ((2ll * bh) * WO + 2ll * w) * C8 + c8;

    stg_evict_first(out + o,             v);  // (2h,   2w)
    stg_evict_first(out + o + C8,        v);  // (2h,   2w+1)
    stg_evict_first(out + o + ROWS,      v);  // (2h+1, 2w)
    stg_evict_first(out + o + ROWS + C8, v);  // (2h+1, 2w+1)
}

extern "C" void kernel_launch(void* const* d_in, const int* in_sizes, int n_in,
                              void* d_out, int out_size)
{
    const v8* in  = (const v8*)d_in[0];
    v8*       out = (v8*)d_out;

    const int threads = 256;
    const long long blocks = N_IN8 / threads;   // 16384
    upsample2x_kernel<<<(unsigned)blocks, threads>>>(in, out);
}